// round 1
// baseline (speedup 1.0000x reference)
#include <cuda_runtime.h>

// RoIAlign (FPN, 4 levels) + 2x2 stride-1 avg epilogue.
// Layout: 1 block per roi (1024 blocks), 1 thread per channel (256 threads).
// Sample metadata (tap indices + bilinear weights, validity folded into
// weights) is computed once per block into shared float4 arrays.

namespace {
constexpr int C = 256;

__global__ __launch_bounds__(256, 4)
void roialign_kernel(const float* __restrict__ f0, const float* __restrict__ f1,
                     const float* __restrict__ f2, const float* __restrict__ f3,
                     const float* __restrict__ rois, float* __restrict__ out)
{
    const int roi = blockIdx.x;
    const int b = roi >> 9;                 // N = 512
    const float* r = rois + roi * 7;
    __shared__ float4 sx[14];               // {x0i, x1i (as int bits), wx0, wx1}
    __shared__ float4 sy[14];

    const int tid = threadIdx.x;
    const int lev = (int)r[6];              // exact small integers stored as float
    const int Wd = 160 >> lev;

    if (tid < 28) {
        const float scale = 8.0f / (float)(1 << lev);
        const bool isx = tid < 14;
        const int k = isx ? tid : tid - 14;
        const float c1 = r[isx ? 1 : 2] * scale;
        const float c2 = r[isx ? 3 : 4] * scale;
        const float bin = fmaxf(c2 - c1, 1.0f) * (1.0f / 7.0f);
        const float off = (float)(k >> 1) + ((k & 1) ? 0.75f : 0.25f);
        const float pos = c1 + off * bin;
        const bool valid = (pos >= -1.0f) && (pos <= (float)Wd);
        const float p = fminf(fmaxf(pos, 0.0f), (float)(Wd - 1));
        const float p0 = floorf(p);
        const int i0 = (int)p0;
        const int i1 = min(i0 + 1, Wd - 1);
        const float l = p - p0;
        float4 v;
        v.x = __int_as_float(i0);
        v.y = __int_as_float(i1);
        v.z = valid ? (1.0f - l) : 0.0f;    // invalid sample -> both weights 0
        v.w = valid ? l : 0.0f;
        if (isx) sx[k] = v; else sy[k] = v;
    }
    __syncthreads();

    const float* fb = (lev == 0) ? f0 : (lev == 1) ? f1 : (lev == 2) ? f2 : f3;
    const int HW = Wd * Wd;
    const float* fc = fb + (size_t)(b * C + tid) * HW;
    float* op = out + (size_t)roi * (C * 36) + tid * 36;

    // Stream pooled 7-wide rows; fuse the 2x2 stride-1 avg pool on the fly.
    float prev[7];
    #pragma unroll 1
    for (int py = 0; py < 7; ++py) {
        float cur[7] = {0, 0, 0, 0, 0, 0, 0};
        #pragma unroll
        for (int s = 0; s < 2; ++s) {
            const float4 yv = sy[py * 2 + s];
            const float* r0 = fc + __float_as_int(yv.x) * Wd;
            const float* r1 = fc + __float_as_int(yv.y) * Wd;
            const float wy0 = yv.z, wy1 = yv.w;
            #pragma unroll
            for (int t = 0; t < 14; ++t) {
                const float4 xv = sx[t];
                const int x0 = __float_as_int(xv.x);
                const int x1 = __float_as_int(xv.y);
                const float a = __ldg(r0 + x0);
                const float bb = __ldg(r0 + x1);
                const float cc = __ldg(r1 + x0);
                const float dd = __ldg(r1 + x1);
                cur[t >> 1] += wy0 * (a * xv.z + bb * xv.w)
                             + wy1 * (cc * xv.z + dd * xv.w);
            }
        }
        if (py > 0) {
            #pragma unroll
            for (int j = 0; j < 6; ++j)
                op[(py - 1) * 6 + j] =
                    0.0625f * (prev[j] + prev[j + 1] + cur[j] + cur[j + 1]);
        }
        #pragma unroll
        for (int j = 0; j < 7; ++j) prev[j] = cur[j];
    }
}
} // namespace

extern "C" void kernel_launch(void* const* d_in, const int* in_sizes, int n_in,
                              void* d_out, int out_size) {
    const float* f0   = (const float*)d_in[0];
    const float* f1   = (const float*)d_in[1];
    const float* f2   = (const float*)d_in[2];
    const float* f3   = (const float*)d_in[3];
    const float* rois = (const float*)d_in[4];
    const int nroi = in_sizes[4] / 7;       // B*N = 1024
    roialign_kernel<<<nroi, 256>>>(f0, f1, f2, f3, rois, (float*)d_out);
}

// round 2
// speedup vs baseline: 6.5918x; 6.5918x over previous
#include <cuda_runtime.h>

// RoIAlign (FPN, 4 levels) + fused 2x2 stride-1 avg epilogue.
// Parallelization: block per roi (1024 blocks, 256 thr = 8 warps).
// Each WARP processes 32 channels serially. Within a warp, lane l (<28)
// owns x-tap column l = 2*t + k (tap t, corner k), so the per-row gather
// of 28 lanes spans only the roi's x-extent -> few L1 wavefronts per LDG
// (vs 32 with thread-per-channel). Pooled bins are formed by a 4-lane
// shuffle reduction; the 2x2 avg pool uses one extra shfl by 4.

namespace {
constexpr int C = 256;

__global__ __launch_bounds__(256, 4)
void roialign_kernel(const float* __restrict__ f0, const float* __restrict__ f1,
                     const float* __restrict__ f2, const float* __restrict__ f3,
                     const float* __restrict__ rois, float* __restrict__ out)
{
    const int roi = blockIdx.x;
    const int b = roi >> 9;                 // N = 512
    const float* r = rois + roi * 7;

    __shared__ int   scol[32];              // column index per lane (clamped)
    __shared__ float swx[32];               // x-weight per lane (0 if invalid)
    __shared__ float4 sy[14];               // {row0*Wd, row1*Wd (int bits), wy0, wy1}

    const int tid = threadIdx.x;
    const int lev = (int)r[6];
    const int Wd = 160 >> lev;

    if (tid < 32) {                         // x-tap setup: lane l = 2*t + k
        int l = tid;
        int t = l >> 1, k = l & 1;
        float w = 0.0f; int col = 0;
        if (l < 28) {
            const float scale = 8.0f / (float)(1 << lev);
            const float c1 = r[1] * scale;
            const float c2 = r[3] * scale;
            const float bin = fmaxf(c2 - c1, 1.0f) * (1.0f / 7.0f);
            const float off = (float)(t >> 1) + ((t & 1) ? 0.75f : 0.25f);
            const float pos = c1 + off * bin;
            const bool valid = (pos >= -1.0f) && (pos <= (float)Wd);
            const float p = fminf(fmaxf(pos, 0.0f), (float)(Wd - 1));
            const float p0 = floorf(p);
            const int i0 = (int)p0;
            const int i1 = min(i0 + 1, Wd - 1);
            const float lx = p - p0;
            col = k ? i1 : i0;
            w = valid ? (k ? lx : 1.0f - lx) : 0.0f;
        }
        scol[l] = col;
        swx[l] = w;
    } else if (tid < 46) {                  // y-sample setup: s = tid - 32
        const int s = tid - 32;
        const float scale = 8.0f / (float)(1 << lev);
        const float c1 = r[2] * scale;
        const float c2 = r[4] * scale;
        const float bin = fmaxf(c2 - c1, 1.0f) * (1.0f / 7.0f);
        const float off = (float)(s >> 1) + ((s & 1) ? 0.75f : 0.25f);
        const float pos = c1 + off * bin;
        const bool valid = (pos >= -1.0f) && (pos <= (float)Wd);
        const float p = fminf(fmaxf(pos, 0.0f), (float)(Wd - 1));
        const float p0 = floorf(p);
        const int i0 = (int)p0;
        const int i1 = min(i0 + 1, Wd - 1);
        const float ly = p - p0;
        float4 v;
        v.x = __int_as_float(i0 * Wd);
        v.y = __int_as_float(i1 * Wd);
        v.z = valid ? (1.0f - ly) : 0.0f;
        v.w = valid ? ly : 0.0f;
        sy[s] = v;
    }
    __syncthreads();

    const float* fb = (lev == 0) ? f0 : (lev == 1) ? f1 : (lev == 2) ? f2 : f3;
    const int HW = Wd * Wd;
    const int warp = tid >> 5;
    const int lane = tid & 31;

    const int mycol = scol[lane];
    const float wcol = swx[lane];
    float* outroi = out + (size_t)roi * (C * 36);

    // Each warp: channels warp*32 .. warp*32+31
    #pragma unroll 1
    for (int i = 0; i < 32; ++i) {
        const int c = warp * 32 + i;
        const float* fc = fb + (size_t)(b * C + c) * HW + mycol;

        float val[7] = {0, 0, 0, 0, 0, 0, 0};
        #pragma unroll
        for (int s = 0; s < 14; ++s) {
            const float4 yv = sy[s];
            const float v0 = __ldg(fc + __float_as_int(yv.x));
            const float v1 = __ldg(fc + __float_as_int(yv.y));
            val[s >> 1] += yv.z * v0 + yv.w * v1;
        }

        // 4-lane group reduction: group l/4 = pooled column px (raw 4x sum)
        float p[7];
        #pragma unroll
        for (int py = 0; py < 7; ++py) {
            float v = val[py] * wcol;
            v += __shfl_down_sync(0xFFFFFFFFu, v, 1);
            v += __shfl_down_sync(0xFFFFFFFFu, v, 2);
            p[py] = v;
        }
        // neighbor pooled column (px+1) for the 2x2 avg pool
        float q[7];
        #pragma unroll
        for (int py = 0; py < 7; ++py)
            q[py] = __shfl_down_sync(0xFFFFFFFFu, p[py], 4);

        if ((lane & 3) == 0 && lane < 24) {
            const int px = lane >> 2;       // 0..5
            float* op = outroi + c * 36 + px;
            #pragma unroll
            for (int py = 0; py < 6; ++py)
                op[py * 6] = 0.0625f * (p[py] + p[py + 1] + q[py] + q[py + 1]);
        }
    }
}
} // namespace

extern "C" void kernel_launch(void* const* d_in, const int* in_sizes, int n_in,
                              void* d_out, int out_size) {
    const float* f0   = (const float*)d_in[0];
    const float* f1   = (const float*)d_in[1];
    const float* f2   = (const float*)d_in[2];
    const float* f3   = (const float*)d_in[3];
    const float* rois = (const float*)d_in[4];
    const int nroi = in_sizes[4] / 7;       // B*N = 1024
    roialign_kernel<<<nroi, 256>>>(f0, f1, f2, f3, rois, (float*)d_out);
}

// round 3
// speedup vs baseline: 7.8432x; 1.1898x over previous
#include <cuda_runtime.h>

// RoIAlign (FPN, 4 levels) + fused 2x2 stride-1 avg epilogue.
// Grid: 4 blocks per roi (channel slices of 64), 256 thr = 8 warps/block,
// each warp handles 8 channels. Lane l (<28) owns x-tap column l = 2*t + k,
// so per-row gathers span only the roi x-extent (few L1 wavefronts/LDG).
// Idle lanes 28-31 alias lane 27's column so they add no extra sector.
// Pooled bins via 4-lane shfl reduction; 2x2 avg pool via one shfl by 4.

namespace {
constexpr int C = 256;

__global__ __launch_bounds__(256, 4)
void roialign_kernel(const float* __restrict__ f0, const float* __restrict__ f1,
                     const float* __restrict__ f2, const float* __restrict__ f3,
                     const float* __restrict__ rois, float* __restrict__ out)
{
    const int roi   = blockIdx.x >> 2;
    const int slice = blockIdx.x & 3;       // 64-channel slice
    const int b = roi >> 9;                 // N = 512
    const float* r = rois + roi * 7;

    __shared__ int   scol[32];              // column index per lane (clamped)
    __shared__ float swx[32];               // x-weight per lane (0 if invalid)
    __shared__ float4 sy[14];               // {row0*Wd, row1*Wd (int bits), wy0, wy1}

    const int tid = threadIdx.x;
    const int lev = (int)r[6];
    const int Wd = 160 >> lev;

    if (tid < 32) {                         // x-tap setup: lane l = 2*t + k
        int l = min(tid, 27);               // idle lanes alias lane 27
        int t = l >> 1, k = l & 1;
        const float scale = 8.0f / (float)(1 << lev);
        const float c1 = r[1] * scale;
        const float c2 = r[3] * scale;
        const float bin = fmaxf(c2 - c1, 1.0f) * (1.0f / 7.0f);
        const float off = (float)(t >> 1) + ((t & 1) ? 0.75f : 0.25f);
        const float pos = c1 + off * bin;
        const bool valid = (pos >= -1.0f) && (pos <= (float)Wd);
        const float p = fminf(fmaxf(pos, 0.0f), (float)(Wd - 1));
        const float p0 = floorf(p);
        const int i0 = (int)p0;
        const int i1 = min(i0 + 1, Wd - 1);
        const float lx = p - p0;
        scol[tid] = k ? i1 : i0;
        swx[tid] = (tid < 28 && valid) ? (k ? lx : 1.0f - lx) : 0.0f;
    } else if (tid < 46) {                  // y-sample setup: s = tid - 32
        const int s = tid - 32;
        const float scale = 8.0f / (float)(1 << lev);
        const float c1 = r[2] * scale;
        const float c2 = r[4] * scale;
        const float bin = fmaxf(c2 - c1, 1.0f) * (1.0f / 7.0f);
        const float off = (float)(s >> 1) + ((s & 1) ? 0.75f : 0.25f);
        const float pos = c1 + off * bin;
        const bool valid = (pos >= -1.0f) && (pos <= (float)Wd);
        const float p = fminf(fmaxf(pos, 0.0f), (float)(Wd - 1));
        const float p0 = floorf(p);
        const int i0 = (int)p0;
        const int i1 = min(i0 + 1, Wd - 1);
        const float ly = p - p0;
        float4 v;
        v.x = __int_as_float(i0 * Wd);
        v.y = __int_as_float(i1 * Wd);
        v.z = valid ? (1.0f - ly) : 0.0f;
        v.w = valid ? ly : 0.0f;
        sy[s] = v;
    }
    __syncthreads();

    const float* fb = (lev == 0) ? f0 : (lev == 1) ? f1 : (lev == 2) ? f2 : f3;
    const int HW = Wd * Wd;
    const int warp = tid >> 5;
    const int lane = tid & 31;

    const int mycol = scol[lane];
    const float wcol = swx[lane];
    float* outroi = out + (size_t)roi * (C * 36);
    const int cbase = slice * 64 + warp * 8;

    // Each warp: 8 consecutive channels
    #pragma unroll 1
    for (int i = 0; i < 8; ++i) {
        const int c = cbase + i;
        const float* fc = fb + (size_t)(b * C + c) * HW + mycol;

        float val[7] = {0, 0, 0, 0, 0, 0, 0};
        #pragma unroll
        for (int s = 0; s < 14; ++s) {
            const float4 yv = sy[s];
            const float v0 = __ldg(fc + __float_as_int(yv.x));
            const float v1 = __ldg(fc + __float_as_int(yv.y));
            val[s >> 1] += yv.z * v0 + yv.w * v1;
        }

        // 4-lane group reduction: group l/4 = pooled column px (raw 4x sum)
        float p[7];
        #pragma unroll
        for (int py = 0; py < 7; ++py) {
            float v = val[py] * wcol;
            v += __shfl_down_sync(0xFFFFFFFFu, v, 1);
            v += __shfl_down_sync(0xFFFFFFFFu, v, 2);
            p[py] = v;
        }
        // neighbor pooled column (px+1) for the 2x2 avg pool
        float q[7];
        #pragma unroll
        for (int py = 0; py < 7; ++py)
            q[py] = __shfl_down_sync(0xFFFFFFFFu, p[py], 4);

        if ((lane & 3) == 0 && lane < 24) {
            const int px = lane >> 2;       // 0..5
            float* op = outroi + c * 36 + px;
            #pragma unroll
            for (int py = 0; py < 6; ++py)
                op[py * 6] = 0.0625f * (p[py] + p[py + 1] + q[py] + q[py + 1]);
        }
    }
}
} // namespace

extern "C" void kernel_launch(void* const* d_in, const int* in_sizes, int n_in,
                              void* d_out, int out_size) {
    const float* f0   = (const float*)d_in[0];
    const float* f1   = (const float*)d_in[1];
    const float* f2   = (const float*)d_in[2];
    const float* f3   = (const float*)d_in[3];
    const float* rois = (const float*)d_in[4];
    const int nroi = in_sizes[4] / 7;       // B*N = 1024
    roialign_kernel<<<nroi * 4, 256>>>(f0, f1, f2, f3, rois, (float*)d_out);
}

// round 4
// speedup vs baseline: 8.3741x; 1.0677x over previous
#include <cuda_runtime.h>

// RoIAlign (FPN, 4 levels) + fused 2x2 stride-1 avg epilogue.
// Grid: 4 blocks per roi (channel slices of 64), 256 thr = 8 warps/block,
// each warp handles 8 channels. Lane l (<28) owns x-tap column l = 2*t + k.
// Fast path (rh <= 14 px): y-sample stride <= 1, so each pooled row's 4
// bilinear rows fit a 3-row window -> <=3 predicated loads per pooled row
// (skip zero-weight rows) instead of 4.
// Pooled bins via 4-lane shfl reduction; 2x2 avg pool via one shfl by 4.

namespace {
constexpr int C = 256;

__global__ __launch_bounds__(256, 5)
void roialign_kernel(const float* __restrict__ f0, const float* __restrict__ f1,
                     const float* __restrict__ f2, const float* __restrict__ f3,
                     const float* __restrict__ rois, float* __restrict__ out)
{
    const int roi   = blockIdx.x >> 2;
    const int slice = blockIdx.x & 3;       // 64-channel slice
    const int b = roi >> 9;                 // N = 512
    const float* r = rois + roi * 7;

    __shared__ int    scol[32];             // column index per lane (clamped)
    __shared__ float  swx[32];              // x-weight per lane (0 if invalid)
    __shared__ float4 sy[14];               // {off0, off1 (int bits), wy0, wy1}
    __shared__ int2   sri[14];              // raw row indices {i0, i1}
    __shared__ float4 spy[7];               // fast: {baseOff bits, w0, w1, w2}

    const int tid = threadIdx.x;
    const int lev = (int)r[6];
    const int Wd = 160 >> lev;
    const float scale = 8.0f / (float)(1 << lev);

    // uniform fast-path condition: sample stride rh/14 <= 1
    const float rh_u = fmaxf(r[4] * scale - r[2] * scale, 1.0f);
    const bool fast = (rh_u <= 14.0f);

    if (tid < 32) {                         // x-tap setup: lane l = 2*t + k
        int l = min(tid, 27);               // idle lanes alias lane 27
        int t = l >> 1, k = l & 1;
        const float c1 = r[1] * scale;
        const float c2 = r[3] * scale;
        const float bin = fmaxf(c2 - c1, 1.0f) * (1.0f / 7.0f);
        const float off = (float)(t >> 1) + ((t & 1) ? 0.75f : 0.25f);
        const float pos = c1 + off * bin;
        const bool valid = (pos >= -1.0f) && (pos <= (float)Wd);
        const float p = fminf(fmaxf(pos, 0.0f), (float)(Wd - 1));
        const float p0 = floorf(p);
        const int i0 = (int)p0;
        const int i1 = min(i0 + 1, Wd - 1);
        const float lx = p - p0;
        scol[tid] = k ? i1 : i0;
        swx[tid] = (tid < 28 && valid) ? (k ? lx : 1.0f - lx) : 0.0f;
    } else if (tid < 46) {                  // y-sample setup: s = tid - 32
        const int s = tid - 32;
        const float c1 = r[2] * scale;
        const float c2 = r[4] * scale;
        const float bin = fmaxf(c2 - c1, 1.0f) * (1.0f / 7.0f);
        const float off = (float)(s >> 1) + ((s & 1) ? 0.75f : 0.25f);
        const float pos = c1 + off * bin;
        const bool valid = (pos >= -1.0f) && (pos <= (float)Wd);
        const float p = fminf(fmaxf(pos, 0.0f), (float)(Wd - 1));
        const float p0 = floorf(p);
        const int i0 = (int)p0;
        const int i1 = min(i0 + 1, Wd - 1);
        const float ly = p - p0;
        float4 v;
        v.x = __int_as_float(i0 * Wd);
        v.y = __int_as_float(i1 * Wd);
        v.z = valid ? (1.0f - ly) : 0.0f;
        v.w = valid ? ly : 0.0f;
        sy[s] = v;
        sri[s] = make_int2(i0, i1);
    }
    __syncthreads();

    if (fast && tid < 7) {                  // build 3-row window per pooled row
        const int s0 = 2 * tid, s1 = s0 + 1;
        const int2 ra = sri[s0];
        const int2 rb = sri[s1];
        const float4 ya = sy[s0];
        const float4 yb = sy[s1];
        const int base = ra.x;              // rows monotone within a bin
        float w[3] = {0.0f, 0.0f, 0.0f};
        w[0] += ya.z;                       // ra.x - base == 0
        w[ra.y - base] += ya.w;
        w[rb.x - base] += yb.z;
        w[rb.y - base] += yb.w;
        float4 e;
        e.x = __int_as_float(base * Wd);
        e.y = w[0]; e.z = w[1]; e.w = w[2];
        spy[tid] = e;
    }
    __syncthreads();

    const float* fb = (lev == 0) ? f0 : (lev == 1) ? f1 : (lev == 2) ? f2 : f3;
    const int HW = Wd * Wd;
    const int warp = tid >> 5;
    const int lane = tid & 31;

    const int mycol = scol[lane];
    const float wcol = swx[lane];
    float* outroi = out + (size_t)roi * (C * 36);
    const int cbase = slice * 64 + warp * 8;

    #pragma unroll 1
    for (int i = 0; i < 8; ++i) {
        const int c = cbase + i;
        const float* fc = fb + (size_t)(b * C + c) * HW + mycol;

        float val[7];
        if (fast) {
            #pragma unroll
            for (int py = 0; py < 7; ++py) {
                const float4 e = spy[py];
                const int bo = __float_as_int(e.x);
                float acc = 0.0f;
                if (e.y != 0.0f) acc += e.y * __ldg(fc + bo);
                if (e.z != 0.0f) acc += e.z * __ldg(fc + bo + Wd);
                if (e.w != 0.0f) acc += e.w * __ldg(fc + bo + 2 * Wd);
                val[py] = acc;
            }
        } else {
            #pragma unroll
            for (int py = 0; py < 7; ++py) val[py] = 0.0f;
            #pragma unroll
            for (int s = 0; s < 14; ++s) {
                const float4 yv = sy[s];
                const float v0 = __ldg(fc + __float_as_int(yv.x));
                const float v1 = __ldg(fc + __float_as_int(yv.y));
                val[s >> 1] += yv.z * v0 + yv.w * v1;
            }
        }

        // 4-lane group reduction: group l/4 = pooled column px (raw 4x sum)
        float p[7];
        #pragma unroll
        for (int py = 0; py < 7; ++py) {
            float v = val[py] * wcol;
            v += __shfl_down_sync(0xFFFFFFFFu, v, 1);
            v += __shfl_down_sync(0xFFFFFFFFu, v, 2);
            p[py] = v;
        }
        // vertical pair sums, then fetch horizontal neighbor group (px+1)
        float u[6];
        #pragma unroll
        for (int j = 0; j < 6; ++j) u[j] = p[j] + p[j + 1];
        #pragma unroll
        for (int j = 0; j < 6; ++j)
            u[j] += __shfl_down_sync(0xFFFFFFFFu, u[j], 4);

        if ((lane & 3) == 0 && lane < 24) {
            const int px = lane >> 2;       // 0..5
            float* op = outroi + c * 36 + px;
            #pragma unroll
            for (int j = 0; j < 6; ++j)
                op[j * 6] = 0.0625f * u[j];
        }
    }
}
} // namespace

extern "C" void kernel_launch(void* const* d_in, const int* in_sizes, int n_in,
                              void* d_out, int out_size) {
    const float* f0   = (const float*)d_in[0];
    const float* f1   = (const float*)d_in[1];
    const float* f2   = (const float*)d_in[2];
    const float* f3   = (const float*)d_in[3];
    const float* rois = (const float*)d_in[4];
    const int nroi = in_sizes[4] / 7;       // B*N = 1024
    roialign_kernel<<<nroi * 4, 256>>>(f0, f1, f2, f3, rois, (float*)d_out);
}

// round 5
// speedup vs baseline: 9.1608x; 1.0939x over previous
#include <cuda_runtime.h>

// RoIAlign (FPN, 4 levels) + fused 2x2 stride-1 avg epilogue.
// Grid: 4 blocks per roi (channel slices of 64), 256 thr = 8 warps/block,
// each warp handles 8 channels, processed 2 at a time (unroll x2) so the
// second channel's gathers issue underneath the first channel's shuffle
// reduction chain (SHFL lat ~26cyc would otherwise serialize the warp).
// Lane l (<28) owns x-tap column l = 2*t + k. Fast path (rh <= 14 px):
// each pooled row's 4 bilinear rows fit a 3-row window -> <=3 predicated
// loads per pooled row. Pooled bins via 4-lane shfl reduction.

namespace {
constexpr int C = 256;

__global__ __launch_bounds__(256, 4)
void roialign_kernel(const float* __restrict__ f0, const float* __restrict__ f1,
                     const float* __restrict__ f2, const float* __restrict__ f3,
                     const float* __restrict__ rois, float* __restrict__ out)
{
    const int roi   = blockIdx.x >> 2;
    const int slice = blockIdx.x & 3;       // 64-channel slice
    const int b = roi >> 9;                 // N = 512
    const float* r = rois + roi * 7;

    __shared__ int    scol[32];             // column index per lane (clamped)
    __shared__ float  swx[32];              // x-weight per lane (0 if invalid)
    __shared__ float4 sy[14];               // {off0, off1 (int bits), wy0, wy1}
    __shared__ int2   sri[14];              // raw row indices {i0, i1}
    __shared__ float4 spy[7];               // fast: {baseOff bits, w0, w1, w2}

    const int tid = threadIdx.x;
    const int lev = (int)r[6];
    const int Wd = 160 >> lev;
    const float scale = 8.0f / (float)(1 << lev);

    // uniform fast-path condition: sample stride rh/14 <= 1
    const float rh_u = fmaxf(r[4] * scale - r[2] * scale, 1.0f);
    const bool fast = (rh_u <= 14.0f);

    if (tid < 32) {                         // x-tap setup: lane l = 2*t + k
        int l = min(tid, 27);               // idle lanes alias lane 27
        int t = l >> 1, k = l & 1;
        const float c1 = r[1] * scale;
        const float c2 = r[3] * scale;
        const float bin = fmaxf(c2 - c1, 1.0f) * (1.0f / 7.0f);
        const float off = (float)(t >> 1) + ((t & 1) ? 0.75f : 0.25f);
        const float pos = c1 + off * bin;
        const bool valid = (pos >= -1.0f) && (pos <= (float)Wd);
        const float p = fminf(fmaxf(pos, 0.0f), (float)(Wd - 1));
        const float p0 = floorf(p);
        const int i0 = (int)p0;
        const int i1 = min(i0 + 1, Wd - 1);
        const float lx = p - p0;
        scol[tid] = k ? i1 : i0;
        swx[tid] = (tid < 28 && valid) ? (k ? lx : 1.0f - lx) : 0.0f;
    } else if (tid < 46) {                  // y-sample setup: s = tid - 32
        const int s = tid - 32;
        const float c1 = r[2] * scale;
        const float c2 = r[4] * scale;
        const float bin = fmaxf(c2 - c1, 1.0f) * (1.0f / 7.0f);
        const float off = (float)(s >> 1) + ((s & 1) ? 0.75f : 0.25f);
        const float pos = c1 + off * bin;
        const bool valid = (pos >= -1.0f) && (pos <= (float)Wd);
        const float p = fminf(fmaxf(pos, 0.0f), (float)(Wd - 1));
        const float p0 = floorf(p);
        const int i0 = (int)p0;
        const int i1 = min(i0 + 1, Wd - 1);
        const float ly = p - p0;
        float4 v;
        v.x = __int_as_float(i0 * Wd);
        v.y = __int_as_float(i1 * Wd);
        v.z = valid ? (1.0f - ly) : 0.0f;
        v.w = valid ? ly : 0.0f;
        sy[s] = v;
        sri[s] = make_int2(i0, i1);
    }
    __syncthreads();

    if (fast && tid < 7) {                  // build 3-row window per pooled row
        const int s0 = 2 * tid, s1 = s0 + 1;
        const int2 ra = sri[s0];
        const int2 rb = sri[s1];
        const float4 ya = sy[s0];
        const float4 yb = sy[s1];
        const int base = ra.x;              // rows monotone within a bin
        float w[3] = {0.0f, 0.0f, 0.0f};
        w[0] += ya.z;                       // ra.x - base == 0
        w[ra.y - base] += ya.w;
        w[rb.x - base] += yb.z;
        w[rb.y - base] += yb.w;
        float4 e;
        e.x = __int_as_float(base * Wd);
        e.y = w[0]; e.z = w[1]; e.w = w[2];
        spy[tid] = e;
    }
    __syncthreads();

    const float* fb = (lev == 0) ? f0 : (lev == 1) ? f1 : (lev == 2) ? f2 : f3;
    const int HW = Wd * Wd;
    const int warp = tid >> 5;
    const int lane = tid & 31;

    const int mycol = scol[lane];
    const float wcol = swx[lane];
    float* outroi = out + (size_t)roi * (C * 36);
    const int cbase = slice * 64 + warp * 8;

    #pragma unroll 1
    for (int i = 0; i < 8; i += 2) {
        const int c0 = cbase + i;
        const float* fcA = fb + (size_t)(b * C + c0) * HW + mycol;
        const float* fcB = fcA + HW;

        float valA[7], valB[7];
        if (fast) {
            #pragma unroll
            for (int py = 0; py < 7; ++py) {
                const float4 e = spy[py];
                const int bo = __float_as_int(e.x);
                float a = 0.0f, bb = 0.0f;
                if (e.y != 0.0f) { a += e.y * __ldg(fcA + bo);
                                   bb += e.y * __ldg(fcB + bo); }
                if (e.z != 0.0f) { a += e.z * __ldg(fcA + bo + Wd);
                                   bb += e.z * __ldg(fcB + bo + Wd); }
                if (e.w != 0.0f) { a += e.w * __ldg(fcA + bo + 2 * Wd);
                                   bb += e.w * __ldg(fcB + bo + 2 * Wd); }
                valA[py] = a;
                valB[py] = bb;
            }
        } else {
            #pragma unroll
            for (int py = 0; py < 7; ++py) { valA[py] = 0.0f; valB[py] = 0.0f; }
            #pragma unroll
            for (int s = 0; s < 14; ++s) {
                const float4 yv = sy[s];
                const int o0 = __float_as_int(yv.x);
                const int o1 = __float_as_int(yv.y);
                const float a0 = __ldg(fcA + o0);
                const float a1 = __ldg(fcA + o1);
                const float b0 = __ldg(fcB + o0);
                const float b1 = __ldg(fcB + o1);
                valA[s >> 1] += yv.z * a0 + yv.w * a1;
                valB[s >> 1] += yv.z * b0 + yv.w * b1;
            }
        }

        // 4-lane group reduction for both channels (independent chains)
        float pA[7], pB[7];
        #pragma unroll
        for (int py = 0; py < 7; ++py) {
            float vA = valA[py] * wcol;
            float vB = valB[py] * wcol;
            vA += __shfl_down_sync(0xFFFFFFFFu, vA, 1);
            vB += __shfl_down_sync(0xFFFFFFFFu, vB, 1);
            vA += __shfl_down_sync(0xFFFFFFFFu, vA, 2);
            vB += __shfl_down_sync(0xFFFFFFFFu, vB, 2);
            pA[py] = vA;
            pB[py] = vB;
        }
        float uA[6], uB[6];
        #pragma unroll
        for (int j = 0; j < 6; ++j) { uA[j] = pA[j] + pA[j + 1];
                                      uB[j] = pB[j] + pB[j + 1]; }
        #pragma unroll
        for (int j = 0; j < 6; ++j) {
            uA[j] += __shfl_down_sync(0xFFFFFFFFu, uA[j], 4);
            uB[j] += __shfl_down_sync(0xFFFFFFFFu, uB[j], 4);
        }

        if ((lane & 3) == 0 && lane < 24) {
            const int px = lane >> 2;       // 0..5
            float* opA = outroi + c0 * 36 + px;
            #pragma unroll
            for (int j = 0; j < 6; ++j) {
                opA[j * 6]      = 0.0625f * uA[j];
                opA[36 + j * 6] = 0.0625f * uB[j];
            }
        }
    }
}
} // namespace

extern "C" void kernel_launch(void* const* d_in, const int* in_sizes, int n_in,
                              void* d_out, int out_size) {
    const float* f0   = (const float*)d_in[0];
    const float* f1   = (const float*)d_in[1];
    const float* f2   = (const float*)d_in[2];
    const float* f3   = (const float*)d_in[3];
    const float* rois = (const float*)d_in[4];
    const int nroi = in_sizes[4] / 7;       // B*N = 1024
    roialign_kernel<<<nroi * 4, 256>>>(f0, f1, f2, f3, rois, (float*)d_out);
}